// round 12
// baseline (speedup 1.0000x reference)
#include <cuda_runtime.h>
#include <cuda_bf16.h>
#include <cstdint>

// ---------------- problem constants ----------------
#define V_DIM 32000
#define H_DIM 4096
#define N_TOK 4096
#define TILE_M 128
#define TILE_N 128
#define KC 64                        // bf16 elems per K stage (128B rows)
#define NITER (H_DIM / KC)           // 64
#define NST 3
#define NUM_VC (V_DIM / TILE_N)      // 250
#define NUM_TB (N_TOK / TILE_M)      // 32

// ---------------- smem layout (NO overlaps: SM_ROWS ends at 1088 < 2048) -----
#define A_BYTES (TILE_M * 128)       // 16384
#define B_BYTES (TILE_N * 128)       // 16384
#define SM_BIAS   64                 // [64, 576)    128 floats
#define SM_ROWS   576                // [576, 1088)  128 floats
#define SM_A      2048
#define SM_B      (SM_A + NST * A_BYTES)
#define SMEM_TOTAL (SM_B + NST * B_BYTES)   // 100352 -> 2 CTAs/SM

// ---------------- device scratch ----------------
__device__ __nv_bfloat16 g_W[(size_t)V_DIM * H_DIM];    // 262 MB
__device__ __nv_bfloat16 g_X[(size_t)N_TOK * H_DIM];    // 33.5 MB
__device__ float         g_part[(size_t)N_TOK * NUM_VC];// 4 MB (sumexp)
__device__ float         g_tgt[N_TOK];                  // fp32 target logits
__device__ float2        g_blk[NUM_TB];

// ---------------- helpers ----------------
__device__ __forceinline__ uint32_t smem_to_u32(const void* p) {
    uint32_t a;
    asm("{ .reg .u64 t; cvta.to.shared.u64 t, %1; cvt.u32.u64 %0, t; }" : "=r"(a) : "l"(p));
    return a;
}

#define CP_ASYNC16(dst, src) \
    asm volatile("cp.async.cg.shared.global [%0], [%1], 16;" :: "r"((uint32_t)(dst)), "l"(src))
#define CP_COMMIT() asm volatile("cp.async.commit_group;" ::: "memory")
#define CP_WAIT2()  asm volatile("cp.async.wait_group 2;" ::: "memory")

#define LDMATRIX_X4(r0, r1, r2, r3, addr) \
    asm volatile("ldmatrix.sync.aligned.m8n8.x4.shared.b16 {%0,%1,%2,%3}, [%4];" \
        : "=r"(r0), "=r"(r1), "=r"(r2), "=r"(r3) : "r"(addr))

#define MMA_16816(d, a0, a1, a2, a3, b0, b1) \
    asm volatile("mma.sync.aligned.m16n8k16.row.col.f32.bf16.bf16.f32 " \
        "{%0,%1,%2,%3}, {%4,%5,%6,%7}, {%8,%9}, {%0,%1,%2,%3};" \
        : "+f"((d)[0]), "+f"((d)[1]), "+f"((d)[2]), "+f"((d)[3]) \
        : "r"(a0), "r"(a1), "r"(a2), "r"(a3), "r"(b0), "r"(b1))

#define SWZ(off) ((off) ^ (((off) >> 3) & 0x70))

// Robust target loading (int64 reference, but JAX may emit int32 without x64).
__device__ __forceinline__ int detect_mode32(const void* p) {
    const long long* q = (const long long*)p;
    #pragma unroll
    for (int i = 0; i < 4; i++) {
        long long v = q[i];
        if ((v < 0 && v != -100ll) || v >= V_DIM) return 1;
    }
    return 0;
}
__device__ __forceinline__ long long load_tgt(const void* p, int i, int mode32) {
    return mode32 ? (long long)((const int*)p)[i] : ((const long long*)p)[i];
}

// ---------------- kernel 1: fp32 -> bf16 convert ----------------
__global__ void cvt4_kernel(const float4* __restrict__ src, uint2* __restrict__ dst, int n4) {
    int i = blockIdx.x * blockDim.x + threadIdx.x;
    if (i < n4) {
        float4 v = src[i];
        __nv_bfloat162 lo = __floats2bfloat162_rn(v.x, v.y);
        __nv_bfloat162 hi = __floats2bfloat162_rn(v.z, v.w);
        uint2 o;
        o.x = *reinterpret_cast<uint32_t*>(&lo);
        o.y = *reinterpret_cast<uint32_t*>(&hi);
        dst[i] = o;
    }
}

// ---------------- kernel 1b: exact fp32 target logits (independent path) -----
__global__ void tgt_kernel(const float* __restrict__ X, const float* __restrict__ W,
                           const float* __restrict__ bias, const void* __restrict__ target) {
    __shared__ float sd[128];
    const int b = blockIdx.x;          // row 0..4095
    const int tid = threadIdx.x;       // 128
    const int mode32 = detect_mode32(target);
    const long long t = load_tgt(target, b, mode32);
    const int tt = (t >= 0 && t < V_DIM) ? (int)t : 0;   // OOB-safe for -100
    const float* xr = X + (size_t)b * H_DIM;
    const float* wr = W + (size_t)tt * H_DIM;
    float a = 0.f;
    for (int h = tid; h < H_DIM; h += 128) a = fmaf(xr[h], wr[h], a);
    sd[tid] = a;
    __syncthreads();
    for (int off = 64; off; off >>= 1) {
        if (tid < off) sd[tid] += sd[tid + off];
        __syncthreads();
    }
    if (tid == 0) g_tgt[b] = sd[0] + bias[tt];
}

// ---------------- stage loader ----------------
__device__ __forceinline__ void load_stage(
    uint32_t aDst, uint32_t bDst,
    const __nv_bfloat16* __restrict__ gA,
    const __nv_bfloat16* __restrict__ gB,
    int tid)
{
    #pragma unroll
    for (int w = 0; w < 4; w++) {
        const int idx = (w << 8) + tid;
        const int row = idx >> 3;
        const int c   = idx & 7;
        const uint32_t soff = (uint32_t)row * 128 + (uint32_t)((c ^ (row & 7)) << 4);
        CP_ASYNC16(aDst + soff, gA + (size_t)row * H_DIM + c * 8);
        CP_ASYNC16(bDst + soff, gB + (size_t)row * H_DIM + c * 8);
    }
}

// ---------------- kernel 2: mma.sync GEMM + sumexp-only epilogue ----------------
__global__ void __launch_bounds__(256, 2)
gemm_ce_kernel(const __nv_bfloat16* __restrict__ gX,
               const __nv_bfloat16* __restrict__ gW,
               const float* __restrict__ bias) {
    extern __shared__ char smem[];
    const uint32_t sb = smem_to_u32(smem);
    const int tid  = threadIdx.x;
    const int wid  = tid >> 5;
    const int lane = tid & 31;
    const int tb = blockIdx.x;
    const int vc = blockIdx.y;

    if (tid < 128) {
        ((float*)(smem + SM_BIAS))[tid] = bias[vc * TILE_N + tid];
        ((float*)(smem + SM_ROWS))[tid] = 0.f;
    }

    const __nv_bfloat16* aSrc = gX + (size_t)(tb * TILE_M) * H_DIM;
    const __nv_bfloat16* bSrc = gW + (size_t)(vc * TILE_N) * H_DIM;

    load_stage(sb + SM_A, sb + SM_B, aSrc, bSrc, tid);
    CP_COMMIT();
    load_stage(sb + SM_A + A_BYTES, sb + SM_B + B_BYTES, aSrc + KC, bSrc + KC, tid);
    CP_COMMIT();

    // warp tiling: 2 (M) x 4 (N) warps; warp tile 64x32
    const int m0 = (wid >> 2) * 64;
    const int n0 = (wid & 3) * 32;
    const int rsel = lane & 15;
    const int csel = (lane >> 4) * 16;

    float acc[4][4][4];
    #pragma unroll
    for (int i = 0; i < 4; i++)
        #pragma unroll
        for (int j = 0; j < 4; j++)
            #pragma unroll
            for (int k = 0; k < 4; k++) acc[i][j][k] = 0.f;

    int s = 0;
    for (int it = 0; it < NITER; it++) {
        const int nx = it + 2;
        if (nx < NITER) {
            const int sn = nx % NST;
            load_stage(sb + SM_A + sn * A_BYTES, sb + SM_B + sn * B_BYTES,
                       aSrc + nx * KC, bSrc + nx * KC, tid);
        }
        CP_COMMIT();
        CP_WAIT2();
        __syncthreads();

        const uint32_t aBase = sb + SM_A + s * A_BYTES;
        const uint32_t bBase = sb + SM_B + s * B_BYTES;

        #pragma unroll
        for (int kk = 0; kk < 4; kk++) {
            const int cb = kk * 32 + csel;
            uint32_t a[4][4], br[2][4];
            #pragma unroll
            for (int mi = 0; mi < 4; mi++) {
                uint32_t off = (uint32_t)(m0 + mi * 16 + rsel) * 128 + cb;
                LDMATRIX_X4(a[mi][0], a[mi][1], a[mi][2], a[mi][3], aBase + SWZ(off));
            }
            #pragma unroll
            for (int ng = 0; ng < 2; ng++) {
                uint32_t off = (uint32_t)(n0 + ng * 16 + rsel) * 128 + cb;
                LDMATRIX_X4(br[ng][0], br[ng][1], br[ng][2], br[ng][3], bBase + SWZ(off));
            }
            #pragma unroll
            for (int mi = 0; mi < 4; mi++) {
                #pragma unroll
                for (int ng = 0; ng < 2; ng++) {
                    MMA_16816(acc[mi][ng * 2 + 0], a[mi][0], a[mi][1], a[mi][2], a[mi][3],
                              br[ng][0], br[ng][2]);
                    MMA_16816(acc[mi][ng * 2 + 1], a[mi][0], a[mi][1], a[mi][2], a[mi][3],
                              br[ng][1], br[ng][3]);
                }
            }
        }
        __syncthreads();
        if (++s == NST) s = 0;
    }

    // ---------------- sumexp-only epilogue (probe-validated shape) ------------
    const float* bcol = (const float*)(smem + SM_BIAS);
    float* sRows = (float*)(smem + SM_ROWS);
    const int quad = lane >> 2, q = lane & 3;

    #pragma unroll
    for (int mi = 0; mi < 4; mi++) {
        const int r0 = m0 + mi * 16 + quad;
        const int r1 = r0 + 8;
        float s0 = 0.f, s1 = 0.f;
        #pragma unroll
        for (int nj = 0; nj < 4; nj++) {
            const int c0 = n0 + nj * 8 + q * 2;
            const int c1 = c0 + 1;
            const float b0f = bcol[c0], b1f = bcol[c1];
            s0 += __expf(acc[mi][nj][0] + b0f) + __expf(acc[mi][nj][1] + b1f);
            s1 += __expf(acc[mi][nj][2] + b0f) + __expf(acc[mi][nj][3] + b1f);
        }
        #pragma unroll
        for (int d = 1; d < 4; d <<= 1) {
            s0 += __shfl_xor_sync(0xffffffffu, s0, d);
            s1 += __shfl_xor_sync(0xffffffffu, s1, d);
        }
        if (q == 0) {
            atomicAdd(&sRows[r0], s0);
            atomicAdd(&sRows[r1], s1);
        }
    }
    __syncthreads();
    if (tid < 128)
        g_part[(size_t)(tb * TILE_M + tid) * NUM_VC + vc] = sRows[tid];
}

// ---------------- kernel 3/4: combine + final mean ----------------
__global__ void reduce1_kernel(const void* __restrict__ target) {
    __shared__ float sn[128], sc[128];
    const int tid = threadIdx.x;
    const int row = blockIdx.x * 128 + tid;
    const int mode32 = detect_mode32(target);
    const float* p = g_part + (size_t)row * NUM_VC;
    float S = 0.f;
    #pragma unroll 5
    for (int j = 0; j < NUM_VC; j++) S += p[j];
    const long long t = load_tgt(target, row, mode32);
    const bool valid = (t != -100ll);
    sn[tid] = valid ? (logf(S) - g_tgt[row]) : 0.f;
    sc[tid] = valid ? 1.f : 0.f;
    __syncthreads();
    for (int off = 64; off; off >>= 1) {
        if (tid < off) { sn[tid] += sn[tid + off]; sc[tid] += sc[tid + off]; }
        __syncthreads();
    }
    if (tid == 0) g_blk[blockIdx.x] = make_float2(sn[0], sc[0]);
}

__global__ void reduce2_kernel(float* __restrict__ out) {
    const int tid = threadIdx.x;  // 32
    float2 v = g_blk[tid];
    float n = v.x, c = v.y;
    #pragma unroll
    for (int off = 16; off; off >>= 1) {
        n += __shfl_down_sync(0xffffffffu, n, off);
        c += __shfl_down_sync(0xffffffffu, c, off);
    }
    if (tid == 0) out[0] = n / c;
}

// ---------------- host side ----------------
extern "C" void kernel_launch(void* const* d_in, const int* in_sizes, int n_in,
                              void* d_out, int out_size) {
    const float* W    = nullptr;
    const float* X    = nullptr;
    const void*  tgt  = nullptr;
    const float* bias = nullptr;
    for (int i = 0; i < n_in; i++) {
        switch (in_sizes[i]) {
            case 131072000: W    = (const float*)d_in[i]; break;
            case 16777216:  X    = (const float*)d_in[i]; break;
            case 4096:      tgt  = d_in[i];               break;
            case 32000:     bias = (const float*)d_in[i]; break;
            default: break;
        }
    }
    if (!W || !X || !tgt || !bias) {
        W    = (const float*)d_in[0];
        X    = (const float*)d_in[1];
        tgt  = d_in[2];
        bias = (const float*)d_in[3];
    }
    float* out = (float*)d_out;

    void *pW = nullptr, *pX = nullptr;
    cudaGetSymbolAddress(&pW, g_W);
    cudaGetSymbolAddress(&pX, g_X);

    const int nW4 = (V_DIM * H_DIM) / 4;
    const int nX4 = (N_TOK * H_DIM) / 4;
    cvt4_kernel<<<(nW4 + 255) / 256, 256>>>((const float4*)W, (uint2*)pW, nW4);
    cvt4_kernel<<<(nX4 + 255) / 256, 256>>>((const float4*)X, (uint2*)pX, nX4);

    tgt_kernel<<<N_TOK, 128>>>(X, W, bias, tgt);

    cudaFuncSetAttribute(gemm_ce_kernel, cudaFuncAttributeMaxDynamicSharedMemorySize, SMEM_TOTAL);
    dim3 grid(NUM_TB, NUM_VC);
    gemm_ce_kernel<<<grid, 256, SMEM_TOTAL>>>(
        (const __nv_bfloat16*)pX, (const __nv_bfloat16*)pW, bias);

    reduce1_kernel<<<NUM_TB, 128>>>(tgt);
    reduce2_kernel<<<1, 32>>>(out);
}